// round 2
// baseline (speedup 1.0000x reference)
#include <cuda_runtime.h>
#include <math.h>

#define CB 4
#define CN 4096
#define CD 256
#define CH 8
#define CDH 32
#define CML 256
#define CBH (CB*CH)
#define CINNER 256

// ---------------- scratch (device globals; no allocation allowed) ----------
__device__ float g_Y   [CB*CN*CD];
__device__ float g_XN  [CB*CN*CD];
__device__ float g_QKV [CB*CN*3*CD];
__device__ float g_Q   [CB*CH*CN*CDH];
__device__ float g_K   [CB*CH*CN*CDH];
__device__ float g_V   [CB*CH*CN*CDH];
__device__ float g_QL  [CBH*CML*CDH];
__device__ float g_KL  [CBH*CML*CDH];
__device__ float g_A1  [(long long)CBH*CN*CML];
__device__ float g_A3  [(long long)CBH*CML*CN];   // reused as tmp1 = A1 @ pinv
__device__ float g_A2  [CBH*CML*CML];
__device__ float g_Zb  [CBH*CML*CML];
__device__ float g_Z2  [CBH*CML*CML];
__device__ float g_XZ  [CBH*CML*CML];
__device__ float g_T1  [CBH*CML*CML];
__device__ float g_T2  [CBH*CML*CML];
__device__ float g_A3V [CBH*CML*CDH];
__device__ float g_OH  [CB*CH*CN*CDH];
__device__ float g_ONBD[CB*CN*CD];
__device__ float g_HID [CB*CN*2*CD];
__device__ float g_gmax1, g_gmax2;

// ---------------- layernorm (D=256, one block per row) ---------------------
__global__ void layernorm_kernel(const float* __restrict__ x,
                                 const float* __restrict__ g,
                                 const float* __restrict__ b,
                                 float* __restrict__ out) {
    __shared__ float s[256];
    long long row = blockIdx.x;
    int tid = threadIdx.x;
    float v = x[row*CD + tid];
    s[tid] = v; __syncthreads();
    for (int o = 128; o > 0; o >>= 1) { if (tid < o) s[tid] += s[tid+o]; __syncthreads(); }
    float mu = s[0] * (1.0f/CD);
    __syncthreads();
    float d = v - mu;
    s[tid] = d*d; __syncthreads();
    for (int o = 128; o > 0; o >>= 1) { if (tid < o) s[tid] += s[tid+o]; __syncthreads(); }
    float inv = rsqrtf(s[0]*(1.0f/CD) + 1e-5f);
    out[row*CD + tid] = d * inv * g[tid] + b[tid];
}

// ---------------- generic batched SGEMM ------------------------------------
// epi: 0 none | 1 C=alpha*I-AB | 2 C=alpha*AB | 3 +bias | 4 +bias+res | 5 gelu(AB+bias)
#define BM 64
#define BN 64
#define BK 16

template<bool TB>
__global__ void __launch_bounds__(256) gemm_kernel(
    const float* __restrict__ A, const float* __restrict__ B, float* __restrict__ C,
    int M, int N, int K,
    long long sA, long long sB, long long sC,
    int epi, float alpha,
    const float* __restrict__ bias, const float* __restrict__ res)
{
    A += (long long)blockIdx.z * sA;
    B += (long long)blockIdx.z * sB;
    C += (long long)blockIdx.z * sC;

    __shared__ __align__(16) float As[BK][BM+4];
    __shared__ __align__(16) float Bs[BK][BN+4];

    int m0 = blockIdx.y * BM;
    int n0 = blockIdx.x * BN;
    int tid = threadIdx.x;
    int tx = tid & 15, ty = tid >> 4;

    float acc[4][4] = {};

    for (int k0 = 0; k0 < K; k0 += BK) {
        #pragma unroll
        for (int i = 0; i < 4; i++) {
            int ii = tid + i*256;
            int m = ii >> 4;
            int kk = ii & 15;
            int gm = m0 + m;
            As[kk][m] = (gm < M) ? A[(long long)gm*K + (k0+kk)] : 0.0f;
        }
        #pragma unroll
        for (int i = 0; i < 4; i++) {
            int ii = tid + i*256;
            if (!TB) {
                int kk = ii >> 6;
                int n  = ii & 63;
                int gn = n0 + n;
                Bs[kk][n] = (gn < N) ? B[(long long)(k0+kk)*N + gn] : 0.0f;
            } else {
                int n  = ii >> 4;
                int kk = ii & 15;
                int gn = n0 + n;
                Bs[kk][n] = (gn < N) ? B[(long long)gn*K + (k0+kk)] : 0.0f;
            }
        }
        __syncthreads();
        #pragma unroll
        for (int kk = 0; kk < BK; kk++) {
            float4 av = *reinterpret_cast<const float4*>(&As[kk][ty<<2]);
            float4 bv = *reinterpret_cast<const float4*>(&Bs[kk][tx<<2]);
            float a[4]  = {av.x, av.y, av.z, av.w};
            float bb[4] = {bv.x, bv.y, bv.z, bv.w};
            #pragma unroll
            for (int i = 0; i < 4; i++)
                #pragma unroll
                for (int j = 0; j < 4; j++)
                    acc[i][j] = fmaf(a[i], bb[j], acc[i][j]);
        }
        __syncthreads();
    }

    #pragma unroll
    for (int i = 0; i < 4; i++) {
        int gm = m0 + (ty<<2) + i;
        if (gm >= M) continue;
        #pragma unroll
        for (int j = 0; j < 4; j++) {
            int gn = n0 + (tx<<2) + j;
            if (gn >= N) continue;
            float v = acc[i][j];
            if      (epi == 1) v = ((gm==gn) ? alpha : 0.0f) - v;
            else if (epi == 2) v *= alpha;
            else if (epi == 3) v += bias[gn];
            else if (epi == 4) v += bias[gn] + res[(long long)gm*N + gn];
            else if (epi == 5) { v += bias[gn]; v = 0.5f*v*(1.0f + erff(v*0.70710678118654752f)); }
            C[(long long)gm*N + gn] = v;
        }
    }
}

// ---------------- misc elementwise ------------------------------------------
__global__ void split_heads_kernel(const float* __restrict__ qkv,
                                   float* __restrict__ q, float* __restrict__ k,
                                   float* __restrict__ v) {
    long long idx = (long long)blockIdx.x*256 + threadIdx.x; // over CB*CH*CN*CDH
    int d = idx & 31;
    long long t = idx >> 5;
    int n = (int)(t & (CN-1));
    t >>= 12;
    int h = (int)(t & 7);
    int b = (int)(t >> 3);
    long long src = ((long long)b*CN + n)*(3*CINNER) + h*CDH + d;
    q[idx] = qkv[src] * 0.17677669529663687f;   // dh^-0.5, dh=32
    k[idx] = qkv[src + CINNER];
    v[idx] = qkv[src + 2*CINNER];
}

__global__ void landmark_kernel(const float* __restrict__ q, const float* __restrict__ k,
                                float* __restrict__ ql, float* __restrict__ kl) {
    long long idx = (long long)blockIdx.x*256 + threadIdx.x; // over CBH*CML*CDH
    int d = idx & 31;
    long long t = idx >> 5;
    int m = (int)(t & (CML-1));
    long long bh = t >> 8;
    long long base = (bh*CN + (long long)m*16)*CDH + d;
    float sq = 0.f, sk = 0.f;
    #pragma unroll
    for (int j = 0; j < 16; j++) { sq += q[base + j*CDH]; sk += k[base + j*CDH]; }
    ql[idx] = sq * 0.0625f;
    kl[idx] = sk * 0.0625f;
}

__global__ void softmax_kernel(float* __restrict__ x, int L) {
    __shared__ float s[256];
    long long row = blockIdx.x;
    float* p = x + row*(long long)L;
    int tid = threadIdx.x;
    float mx = -3.4e38f;
    for (int j = tid; j < L; j += 256) mx = fmaxf(mx, p[j]);
    s[tid] = mx; __syncthreads();
    for (int o = 128; o > 0; o >>= 1) { if (tid < o) s[tid] = fmaxf(s[tid], s[tid+o]); __syncthreads(); }
    mx = s[0]; __syncthreads();
    float sum = 0.f;
    for (int j = tid; j < L; j += 256) { float e = __expf(p[j]-mx); p[j] = e; sum += e; }
    s[tid] = sum; __syncthreads();
    for (int o = 128; o > 0; o >>= 1) { if (tid < o) s[tid] += s[tid+o]; __syncthreads(); }
    float inv = 1.0f / s[0];
    for (int j = tid; j < L; j += 256) p[j] *= inv;
}

// ---------------- pinv scale (GLOBAL max across B,H) ------------------------
__global__ void zero_gmax_kernel() { g_gmax1 = 0.f; g_gmax2 = 0.f; }

__global__ void abs_rowsum_max_kernel(const float* __restrict__ x) {
    __shared__ float s[256];
    long long row = blockIdx.x; // CBH*CML
    int tid = threadIdx.x;
    float v = fabsf(x[row*CML + tid]);
    s[tid] = v; __syncthreads();
    for (int o = 128; o > 0; o >>= 1) { if (tid < o) s[tid] += s[tid+o]; __syncthreads(); }
    if (tid == 0) atomicMax((int*)&g_gmax1, __float_as_int(s[0]));
}

__global__ void abs_colsum_max_kernel(const float* __restrict__ x) {
    const float* p = x + (long long)blockIdx.x*CML*CML;
    int j = threadIdx.x;
    float s = 0.f;
    for (int i = 0; i < CML; i++) s += fabsf(p[i*CML + j]);
    atomicMax((int*)&g_gmax2, __float_as_int(s));
}

__global__ void zinit_kernel(const float* __restrict__ x, float* __restrict__ z) {
    long long idx = (long long)blockIdx.x*256 + threadIdx.x; // CBH*CML*CML
    int j = (int)(idx & 255);
    int i = (int)((idx >> 8) & 255);
    long long bh = idx >> 16;
    float denom = g_gmax1 * g_gmax2;
    z[idx] = x[(bh << 16) + ((long long)j << 8) + i] / denom;
}

__global__ void idsub_kernel(const float* __restrict__ a, float* __restrict__ c, float alpha) {
    long long idx = (long long)blockIdx.x*256 + threadIdx.x;
    int j = (int)(idx & 255);
    int i = (int)((idx >> 8) & 255);
    c[idx] = ((i==j) ? alpha : 0.0f) - a[idx];
}

// ---------------- depthwise conv (k=33, pad=16) + merge ---------------------
__global__ void conv_add_kernel(const float* __restrict__ v, const float* __restrict__ w,
                                float* __restrict__ oh) {
    long long idx = (long long)blockIdx.x*256 + threadIdx.x; // CB*CH*CN*CDH
    int d = (int)(idx & 31);
    long long t = idx >> 5;
    int n = (int)(t & (CN-1));
    long long bh = t >> 12;
    int h = (int)(bh & 7);
    const float* wp = w + h*33;
    const float* vp = v + bh*(long long)CN*CDH + d;
    float s = 0.f;
    #pragma unroll
    for (int tt = 0; tt < 33; tt++) {
        int nn = n + tt - 16;
        if (nn >= 0 && nn < CN) s += vp[(long long)nn*CDH] * wp[tt];
    }
    oh[idx] += s;
}

__global__ void merge_heads_kernel(const float* __restrict__ oh, float* __restrict__ out) {
    long long idx = (long long)blockIdx.x*256 + threadIdx.x; // CB*CN*CD
    int d = (int)(idx & 31);
    long long t = idx >> 5;
    int h = (int)(t & 7);
    t >>= 3;
    int n = (int)(t & (CN-1));
    int b = (int)(t >> 12);
    out[idx] = oh[((((long long)b*CH + h)*CN) + n)*CDH + d];
}

// ---------------- host orchestration ----------------------------------------
extern "C" void kernel_launch(void* const* d_in, const int* in_sizes, int n_in,
                              void* d_out, int out_size) {
    const float* x     = (const float*)d_in[0];
    const float* ln1_g = (const float*)d_in[1];
    const float* ln1_b = (const float*)d_in[2];
    const float* w_qkv = (const float*)d_in[3];
    const float* w_out = (const float*)d_in[4];
    const float* b_out = (const float*)d_in[5];
    const float* res_w = (const float*)d_in[6];
    const float* ln2_g = (const float*)d_in[7];
    const float* ln2_b = (const float*)d_in[8];
    const float* w1    = (const float*)d_in[9];
    const float* b1    = (const float*)d_in[10];
    const float* w2    = (const float*)d_in[11];
    const float* b2    = (const float*)d_in[12];

    float *Y,*XN,*QKV,*Q,*K,*V,*QL,*KL,*A1,*A3,*A2,*Zb,*Z2,*XZ,*T1,*T2,*A3V,*OH,*ONBD,*HID;
    cudaGetSymbolAddress((void**)&Y,   g_Y);
    cudaGetSymbolAddress((void**)&XN,  g_XN);
    cudaGetSymbolAddress((void**)&QKV, g_QKV);
    cudaGetSymbolAddress((void**)&Q,   g_Q);
    cudaGetSymbolAddress((void**)&K,   g_K);
    cudaGetSymbolAddress((void**)&V,   g_V);
    cudaGetSymbolAddress((void**)&QL,  g_QL);
    cudaGetSymbolAddress((void**)&KL,  g_KL);
    cudaGetSymbolAddress((void**)&A1,  g_A1);
    cudaGetSymbolAddress((void**)&A3,  g_A3);
    cudaGetSymbolAddress((void**)&A2,  g_A2);
    cudaGetSymbolAddress((void**)&Zb,  g_Zb);
    cudaGetSymbolAddress((void**)&Z2,  g_Z2);
    cudaGetSymbolAddress((void**)&XZ,  g_XZ);
    cudaGetSymbolAddress((void**)&T1,  g_T1);
    cudaGetSymbolAddress((void**)&T2,  g_T2);
    cudaGetSymbolAddress((void**)&A3V, g_A3V);
    cudaGetSymbolAddress((void**)&OH,  g_OH);
    cudaGetSymbolAddress((void**)&ONBD,g_ONBD);
    cudaGetSymbolAddress((void**)&HID, g_HID);

    cudaMemcpyAsync(Y, x, sizeof(float)*(size_t)CB*CN*CD, cudaMemcpyDeviceToDevice);

    const long long MM = (long long)CML*CML;

    for (int blk = 0; blk < 2; blk++) {
        const float* p_ln1g = ln1_g + blk*CD;
        const float* p_ln1b = ln1_b + blk*CD;
        const float* p_wqkv = w_qkv + (long long)blk*CD*3*CINNER;
        const float* p_wout = w_out + (long long)blk*CINNER*CD;
        const float* p_bout = b_out + blk*CD;
        const float* p_resw = res_w + blk*CH*33;
        const float* p_ln2g = ln2_g + blk*CD;
        const float* p_ln2b = ln2_b + blk*CD;
        const float* p_w1   = w1 + (long long)blk*CD*2*CD;
        const float* p_b1   = b1 + blk*2*CD;
        const float* p_w2   = w2 + (long long)blk*2*CD*CD;
        const float* p_b2   = b2 + blk*CD;

        // LN1 -> XN
        layernorm_kernel<<<CB*CN, 256>>>(Y, p_ln1g, p_ln1b, XN);

        // QKV = XN @ w_qkv  [16384, 768]
        gemm_kernel<false><<<dim3(12, 256, 1), 256>>>(XN, p_wqkv, QKV,
            CB*CN, 3*CINNER, CD, 0, 0, 0, 0, 0.f, nullptr, nullptr);

        split_heads_kernel<<<(CB*CH*CN*CDH)/256, 256>>>(QKV, Q, K, V);
        landmark_kernel<<<(CBH*CML*CDH)/256, 256>>>(Q, K, QL, KL);

        // attn1 = softmax(Q @ KL^T)  [bh][4096, 256]
        gemm_kernel<true><<<dim3(4, 64, CBH), 256>>>(Q, KL, A1,
            CN, CML, CDH, (long long)CN*CDH, (long long)CML*CDH, (long long)CN*CML,
            0, 0.f, nullptr, nullptr);
        softmax_kernel<<<CBH*CN, 256>>>(A1, CML);

        // attn2 = softmax(QL @ KL^T) [bh][256, 256]
        gemm_kernel<true><<<dim3(4, 4, CBH), 256>>>(QL, KL, A2,
            CML, CML, CDH, (long long)CML*CDH, (long long)CML*CDH, MM,
            0, 0.f, nullptr, nullptr);
        softmax_kernel<<<CBH*CML, 256>>>(A2, CML);

        // attn3 = softmax(QL @ K^T)  [bh][256, 4096]
        gemm_kernel<true><<<dim3(64, 4, CBH), 256>>>(QL, K, A3,
            CML, CN, CDH, (long long)CML*CDH, (long long)CN*CDH, (long long)CML*CN,
            0, 0.f, nullptr, nullptr);
        softmax_kernel<<<CBH*CML, 256>>>(A3, CN);

        // ---- Moore-Penrose pinv of attn2 (global-max scale) ----
        zero_gmax_kernel<<<1, 1>>>();
        abs_rowsum_max_kernel<<<CBH*CML, 256>>>(A2);
        abs_colsum_max_kernel<<<CBH, 256>>>(A2);
        zinit_kernel<<<(int)((CBH*MM)/256), 256>>>(A2, Zb);

        float* zc = Zb; float* zn = Z2;
        for (int it = 0; it < 6; it++) {
            gemm_kernel<false><<<dim3(4, 4, CBH), 256>>>(A2, zc, XZ,
                CML, CML, CML, MM, MM, MM, 0, 0.f, nullptr, nullptr);
            idsub_kernel<<<(int)((CBH*MM)/256), 256>>>(XZ, T1, 7.0f);
            gemm_kernel<false><<<dim3(4, 4, CBH), 256>>>(XZ, T1, T2,
                CML, CML, CML, MM, MM, MM, 1, 15.0f, nullptr, nullptr);
            gemm_kernel<false><<<dim3(4, 4, CBH), 256>>>(XZ, T2, T1,
                CML, CML, CML, MM, MM, MM, 1, 13.0f, nullptr, nullptr);
            gemm_kernel<false><<<dim3(4, 4, CBH), 256>>>(zc, T1, zn,
                CML, CML, CML, MM, MM, MM, 2, 0.25f, nullptr, nullptr);
            float* t = zc; zc = zn; zn = t;
        }

        // A3V = attn3 @ V  [bh][256, 32]
        gemm_kernel<false><<<dim3(1, 4, CBH), 256>>>(A3, V, A3V,
            CML, CDH, CN, (long long)CML*CN, (long long)CN*CDH, (long long)CML*CDH,
            0, 0.f, nullptr, nullptr);

        // tmp1 = attn1 @ pinv  [bh][4096, 256]   (A3 buffer reused as output)
        gemm_kernel<false><<<dim3(4, 64, CBH), 256>>>(A1, zc, A3,
            CN, CML, CML, (long long)CN*CML, MM, (long long)CN*CML,
            0, 0.f, nullptr, nullptr);

        // OH = tmp1 @ A3V   [bh][4096, 32]
        gemm_kernel<false><<<dim3(1, 64, CBH), 256>>>(A3, A3V, OH,
            CN, CDH, CML, (long long)CN*CML, (long long)CML*CDH, (long long)CN*CDH,
            0, 0.f, nullptr, nullptr);

        // OH += depthwise conv(V), merge heads
        conv_add_kernel<<<(CB*CH*CN*CDH)/256, 256>>>(V, p_resw, OH);
        merge_heads_kernel<<<(CB*CN*CD)/256, 256>>>(OH, ONBD);

        // Y = Y + ONBD @ w_out + b_out
        gemm_kernel<false><<<dim3(4, 256, 1), 256>>>(ONBD, p_wout, Y,
            CB*CN, CD, CINNER, 0, 0, 0, 4, 0.f, p_bout, Y);

        // MLP
        layernorm_kernel<<<CB*CN, 256>>>(Y, p_ln2g, p_ln2b, XN);
        gemm_kernel<false><<<dim3(8, 256, 1), 256>>>(XN, p_w1, HID,
            CB*CN, 2*CD, CD, 0, 0, 0, 5, 0.f, p_b1, nullptr);
        gemm_kernel<false><<<dim3(4, 256, 1), 256>>>(HID, p_w2, Y,
            CB*CN, CD, 2*CD, 0, 0, 0, 4, 0.f, p_b2, Y);
    }

    cudaMemcpyAsync(d_out, Y, sizeof(float)*(size_t)CB*CN*CD, cudaMemcpyDeviceToDevice);
}